// round 3
// baseline (speedup 1.0000x reference)
#include <cuda_runtime.h>
#include <math.h>

#define N_NODES  100000
#define N_EDGES  1600000
#define N_GRAPHS 2048
#define H        256

// ---------------- scratch (device globals; no allocs allowed) ----------------
__device__ float g_deg[N_NODES];
__device__ float g_dinv[N_NODES];
__device__ float g_bufA[(size_t)N_NODES * H];   // hs = (h @ W) * dinv[row]
__device__ float g_bufB[(size_t)N_NODES * H];   // accumulator (init = hs, self-loop)
__device__ float g_bufC[(size_t)N_NODES * H];   // h1 after relu
__device__ float g_gsum[N_GRAPHS * H];
__device__ float g_gcnt[N_GRAPHS];

// ---------------- kernels ----------------

__global__ void zero_kernel() {
    int i = blockIdx.x * blockDim.x + threadIdx.x;     // grid covers N_GRAPHS*H = 524288
    if (i < N_NODES)      g_deg[i]  = 0.f;
    if (i < N_GRAPHS * H) g_gsum[i] = 0.f;
    if (i < N_GRAPHS)     g_gcnt[i] = 0.f;
}

// NOTE: edge_index / batch are int32 on device (JAX x64 disabled canonicalizes
// jnp.int64 -> int32).
__global__ void deg_kernel(const int* __restrict__ dst) {
    int e = blockIdx.x * blockDim.x + threadIdx.x;
    if (e < N_EDGES) atomicAdd(&g_deg[dst[e]], 1.0f);
}

__global__ void prep_kernel(const int* __restrict__ batch) {
    int i = blockIdx.x * blockDim.x + threadIdx.x;
    if (i < N_NODES) {
        // deg includes the self-loop (+1); always >= 1 so max(.,1) is implicit
        g_dinv[i] = rsqrtf(g_deg[i] + 1.0f);
        atomicAdd(&g_gcnt[batch[i]], 1.0f);
    }
}

// C1 = C2 = (A[M,K] @ B[K,256]) * dinv[row]   (dual store: C2 doubles as the
// scatter accumulator pre-initialized with the self-loop contribution)
__global__ void __launch_bounds__(256, 2)
sgemm_scale_dual(const float* __restrict__ A, const float* __restrict__ B,
                 const float* __restrict__ dinv,
                 float* __restrict__ C1, float* __restrict__ C2,
                 int M, int K)
{
    const int N = H;
    __shared__ float As[8][132];   // padded: kills STS bank conflicts
    __shared__ float Bs[8][128];

    const int tid  = threadIdx.x;
    const int brow = blockIdx.x * 128;
    const int bcol = blockIdx.y * 128;
    const int tx   = tid & 15;     // strided 8x8 thread tile: cols tx + j*16
    const int ty   = tid >> 4;     //                          rows ty + i*16

    float acc[8][8];
#pragma unroll
    for (int i = 0; i < 8; ++i)
#pragma unroll
        for (int j = 0; j < 8; ++j) acc[i][j] = 0.f;

    const int a_row = tid >> 1;
    const int a_col = (tid & 1) * 4;
    const int b_row = tid >> 5;
    const int b_col = (tid & 31) * 4;

    const bool a_ok = (brow + a_row) < M;
    const float* Aptr = A + (size_t)(brow + a_row) * K + a_col;

    for (int k0 = 0; k0 < K; k0 += 8) {
        float4 av = a_ok ? *(const float4*)(Aptr + k0) : make_float4(0.f, 0.f, 0.f, 0.f);
        As[a_col + 0][a_row] = av.x;
        As[a_col + 1][a_row] = av.y;
        As[a_col + 2][a_row] = av.z;
        As[a_col + 3][a_row] = av.w;
        *(float4*)&Bs[b_row][b_col] =
            *(const float4*)(B + (size_t)(k0 + b_row) * N + bcol + b_col);
        __syncthreads();
#pragma unroll
        for (int kk = 0; kk < 8; ++kk) {
            float ar[8], br[8];
#pragma unroll
            for (int i = 0; i < 8; ++i) ar[i] = As[kk][ty + i * 16];
#pragma unroll
            for (int j = 0; j < 8; ++j) br[j] = Bs[kk][tx + j * 16];
#pragma unroll
            for (int i = 0; i < 8; ++i)
#pragma unroll
                for (int j = 0; j < 8; ++j)
                    acc[i][j] = fmaf(ar[i], br[j], acc[i][j]);
        }
        __syncthreads();
    }

#pragma unroll
    for (int i = 0; i < 8; ++i) {
        int r = brow + ty + i * 16;
        if (r < M) {
            float s = dinv[r];
            size_t base = (size_t)r * N + bcol + tx;
#pragma unroll
            for (int j = 0; j < 8; ++j) {
                float v = acc[i][j] * s;
                C1[base + j * 16] = v;
                C2[base + j * 16] = v;
            }
        }
    }
}

// acc[dst] += hs[src]   (64 float4 lanes per edge, vectorized L2 reduction)
__global__ void scatter_kernel(const float* __restrict__ hs, float* __restrict__ acc,
                               const int* __restrict__ src,
                               const int* __restrict__ dst)
{
    unsigned tid = blockIdx.x * blockDim.x + threadIdx.x;   // exactly N_EDGES*64
    int e = tid >> 6;
    int q = (tid & 63) << 2;
    int s = src[e];
    int d = dst[e];
    float4 v = *(const float4*)(hs + (size_t)s * H + q);
    float* p = acc + (size_t)d * H + q;
    asm volatile("red.global.add.v4.f32 [%0], {%1, %2, %3, %4};"
                 :: "l"(p), "f"(v.x), "f"(v.y), "f"(v.z), "f"(v.w) : "memory");
}

// out = relu(dinv[row]*acc + bias)
__global__ void relu_kernel(const float* __restrict__ acc, const float* __restrict__ dinv,
                            const float* __restrict__ bias, float* __restrict__ out)
{
    unsigned tid = blockIdx.x * blockDim.x + threadIdx.x;   // exactly N_NODES*64
    int n = tid >> 6;
    int q = (tid & 63) << 2;
    float dv = dinv[n];
    float4 a = *(const float4*)(acc + (size_t)n * H + q);
    const float4 b = *(const float4*)(bias + q);
    float4 v;
    v.x = fmaxf(fmaf(dv, a.x, b.x), 0.f);
    v.y = fmaxf(fmaf(dv, a.y, b.y), 0.f);
    v.z = fmaxf(fmaf(dv, a.z, b.z), 0.f);
    v.w = fmaxf(fmaf(dv, a.w, b.w), 0.f);
    *(float4*)(out + (size_t)n * H + q) = v;
}

// h2 = relu(dinv*acc + b2); gsum[batch[n]] += h2   (fused second-layer epilogue + pool)
__global__ void pool_kernel(const float* __restrict__ acc, const float* __restrict__ dinv,
                            const float* __restrict__ bias,
                            const int* __restrict__ batch,
                            float* __restrict__ gsum)
{
    unsigned tid = blockIdx.x * blockDim.x + threadIdx.x;   // exactly N_NODES*64
    int n = tid >> 6;
    int q = (tid & 63) << 2;
    float dv = dinv[n];
    float4 a = *(const float4*)(acc + (size_t)n * H + q);
    const float4 b = *(const float4*)(bias + q);
    float4 v;
    v.x = fmaxf(fmaf(dv, a.x, b.x), 0.f);
    v.y = fmaxf(fmaf(dv, a.y, b.y), 0.f);
    v.z = fmaxf(fmaf(dv, a.z, b.z), 0.f);
    v.w = fmaxf(fmaf(dv, a.w, b.w), 0.f);
    int g = batch[n];
    float* p = gsum + (size_t)g * H + q;
    asm volatile("red.global.add.v4.f32 [%0], {%1, %2, %3, %4};"
                 :: "l"(p), "f"(v.x), "f"(v.y), "f"(v.z), "f"(v.w) : "memory");
}

// per graph: g = gsum/max(cnt,1); logits = g@Wc + bc; log_softmax(64)
__global__ void classify_kernel(const float* __restrict__ gsum, const float* __restrict__ gcnt,
                                const float* __restrict__ Wc, const float* __restrict__ bc,
                                float* __restrict__ out)
{
    int gid = blockIdx.x;
    int j = threadIdx.x;                       // 64 threads
    __shared__ float sg[H];
    __shared__ float red2[2];

    float inv = 1.0f / fmaxf(gcnt[gid], 1.0f);
    for (int c = j; c < H; c += 64) sg[c] = gsum[(size_t)gid * H + c] * inv;
    __syncthreads();

    float acc = bc[j];
#pragma unroll
    for (int c = 0; c < H; ++c)
        acc = fmaf(sg[c], Wc[c * 64 + j], acc);

    // block max over 64 threads
    float m = acc;
#pragma unroll
    for (int o = 16; o; o >>= 1) m = fmaxf(m, __shfl_xor_sync(0xffffffffu, m, o));
    if ((j & 31) == 0) red2[j >> 5] = m;
    __syncthreads();
    m = fmaxf(red2[0], red2[1]);
    __syncthreads();

    float e = expf(acc - m);
    float s = e;
#pragma unroll
    for (int o = 16; o; o >>= 1) s += __shfl_xor_sync(0xffffffffu, s, o);
    if ((j & 31) == 0) red2[j >> 5] = s;
    __syncthreads();
    s = red2[0] + red2[1];

    out[(size_t)gid * 64 + j] = acc - m - logf(s);
}

// ---------------- launch ----------------
extern "C" void kernel_launch(void* const* d_in, const int* in_sizes, int n_in,
                              void* d_out, int out_size)
{
    const float* x     = (const float*)d_in[0];
    const int*   eidx  = (const int*)d_in[1];     // int32 (JAX canonicalized)
    const int*   batch = (const int*)d_in[2];     // int32
    const float* W1    = (const float*)d_in[3];
    const float* b1    = (const float*)d_in[4];
    const float* W2    = (const float*)d_in[5];
    const float* b2    = (const float*)d_in[6];
    const float* Wc    = (const float*)d_in[7];
    const float* bc    = (const float*)d_in[8];
    float*       out   = (float*)d_out;

    const int* src = eidx;
    const int* dst = eidx + N_EDGES;

    float *bufA, *bufB, *bufC, *dinv, *gsum, *gcnt;
    cudaGetSymbolAddress((void**)&bufA, g_bufA);
    cudaGetSymbolAddress((void**)&bufB, g_bufB);
    cudaGetSymbolAddress((void**)&bufC, g_bufC);
    cudaGetSymbolAddress((void**)&dinv, g_dinv);
    cudaGetSymbolAddress((void**)&gsum, g_gsum);
    cudaGetSymbolAddress((void**)&gcnt, g_gcnt);

    zero_kernel<<<(N_GRAPHS * H) / 256, 256>>>();
    deg_kernel<<<(N_EDGES + 255) / 256, 256>>>(dst);
    prep_kernel<<<(N_NODES + 255) / 256, 256>>>(batch);

    dim3 ggrid((N_NODES + 127) / 128, H / 128);

    // layer 1: hs1 -> bufA, acc (self-loop init) -> bufB
    sgemm_scale_dual<<<ggrid, 256>>>(x, W1, dinv, bufA, bufB, N_NODES, 128);
    scatter_kernel<<<(N_EDGES * 64) / 256, 256>>>(bufA, bufB, src, dst);
    relu_kernel<<<(N_NODES * 64) / 256, 256>>>(bufB, dinv, b1, bufC);

    // layer 2
    sgemm_scale_dual<<<ggrid, 256>>>(bufC, W2, dinv, bufA, bufB, N_NODES, 256);
    scatter_kernel<<<(N_EDGES * 64) / 256, 256>>>(bufA, bufB, src, dst);

    // fused relu + mean-pool accumulation
    pool_kernel<<<(N_NODES * 64) / 256, 256>>>(bufB, dinv, b2, batch, gsum);

    // classifier + log_softmax
    classify_kernel<<<N_GRAPHS, 64>>>(gsum, gcnt, Wc, bc, out);
}

// round 4
// speedup vs baseline: 2.0141x; 2.0141x over previous
#include <cuda_runtime.h>
#include <math.h>

#define N_NODES  100000
#define N_EDGES  1600000
#define N_GRAPHS 2048
#define H        256

#define SCAN_NBLK ((N_NODES + 1023) / 1024)   // 98 blocks of 1024

// ---------------- scratch (device globals; no allocs allowed) ----------------
__device__ int   g_ideg[N_NODES];
__device__ int   g_off[N_NODES];
__device__ int   g_cursor[N_NODES];
__device__ int   g_csr[N_EDGES];
__device__ int   g_bsum[SCAN_NBLK];
__device__ int   g_bscan[SCAN_NBLK];
__device__ float g_dinv[N_NODES];
__device__ float g_bufA[(size_t)N_NODES * H];   // hs = (h @ W) * dinv[row]
__device__ float g_bufC[(size_t)N_NODES * H];   // h1 after relu
__device__ float g_gsum[N_GRAPHS * H];
__device__ float g_gcnt[N_GRAPHS];

// ---------------- prep kernels ----------------

__global__ void zero_kernel() {
    int i = blockIdx.x * blockDim.x + threadIdx.x;     // grid covers N_GRAPHS*H = 524288
    if (i < N_NODES) { g_ideg[i] = 0; g_cursor[i] = 0; }
    if (i < N_GRAPHS * H) g_gsum[i] = 0.f;
    if (i < N_GRAPHS)     g_gcnt[i] = 0.f;
}

// edge_index / batch are int32 on device (JAX x64 disabled)
__global__ void deg_kernel(const int* __restrict__ dst) {
    int e = blockIdx.x * blockDim.x + threadIdx.x;
    if (e < N_EDGES) atomicAdd(&g_ideg[dst[e]], 1);
}

// ---- 3-kernel exclusive scan of g_ideg -> g_off ----
__global__ void scan1_kernel() {
    __shared__ int sh[256];
    int tid = threadIdx.x;
    int base = blockIdx.x * 1024 + tid * 4;
    int v[4]; int s = 0;
#pragma unroll
    for (int k = 0; k < 4; ++k) {
        int i = base + k;
        v[k] = (i < N_NODES) ? g_ideg[i] : 0;
        s += v[k];
    }
    sh[tid] = s; __syncthreads();
#pragma unroll
    for (int o = 1; o < 256; o <<= 1) {
        int t = (tid >= o) ? sh[tid - o] : 0;
        __syncthreads(); sh[tid] += t; __syncthreads();
    }
    int run = sh[tid] - s;      // exclusive prefix of this thread's segment
#pragma unroll
    for (int k = 0; k < 4; ++k) {
        int i = base + k;
        if (i < N_NODES) g_off[i] = run;
        run += v[k];
    }
    if (tid == 255) g_bsum[blockIdx.x] = sh[255];
}

__global__ void scan2_kernel() {
    __shared__ int sh[128];
    int tid = threadIdx.x;
    int v = (tid < SCAN_NBLK) ? g_bsum[tid] : 0;
    sh[tid] = v; __syncthreads();
#pragma unroll
    for (int o = 1; o < 128; o <<= 1) {
        int t = (tid >= o) ? sh[tid - o] : 0;
        __syncthreads(); sh[tid] += t; __syncthreads();
    }
    if (tid < SCAN_NBLK) g_bscan[tid] = sh[tid] - v;
}

__global__ void scan3_kernel() {
    int i = blockIdx.x * blockDim.x + threadIdx.x;
    if (i < N_NODES) g_off[i] += g_bscan[i >> 10];
}

// counting-sort edges by destination: g_csr holds src ids grouped by dst
__global__ void fill_kernel(const int* __restrict__ src, const int* __restrict__ dst) {
    int e = blockIdx.x * blockDim.x + threadIdx.x;
    if (e < N_EDGES) {
        int d = dst[e];
        int pos = g_off[d] + atomicAdd(&g_cursor[d], 1);
        g_csr[pos] = src[e];
    }
}

__global__ void prep_kernel(const int* __restrict__ batch) {
    int i = blockIdx.x * blockDim.x + threadIdx.x;
    if (i < N_NODES) {
        g_dinv[i] = rsqrtf((float)g_ideg[i] + 1.0f);   // +1 self-loop, always >= 1
        atomicAdd(&g_gcnt[batch[i]], 1.0f);
    }
}

// ---------------- GEMM: C = (A[M,K] @ B[K,256]) * dinv[row] ----------------
__global__ void __launch_bounds__(256, 2)
sgemm_scale(const float* __restrict__ A, const float* __restrict__ B,
            const float* __restrict__ dinv, float* __restrict__ C,
            int M, int K)
{
    const int N = H;
    __shared__ float As[8][132];
    __shared__ float Bs[8][128];

    const int tid  = threadIdx.x;
    const int brow = blockIdx.x * 128;
    const int bcol = blockIdx.y * 128;
    const int tx   = tid & 15;
    const int ty   = tid >> 4;

    float acc[8][8];
#pragma unroll
    for (int i = 0; i < 8; ++i)
#pragma unroll
        for (int j = 0; j < 8; ++j) acc[i][j] = 0.f;

    const int a_row = tid >> 1;
    const int a_col = (tid & 1) * 4;
    const int b_row = tid >> 5;
    const int b_col = (tid & 31) * 4;

    const bool a_ok = (brow + a_row) < M;
    const float* Aptr = A + (size_t)(brow + a_row) * K + a_col;

    for (int k0 = 0; k0 < K; k0 += 8) {
        float4 av = a_ok ? *(const float4*)(Aptr + k0) : make_float4(0.f, 0.f, 0.f, 0.f);
        As[a_col + 0][a_row] = av.x;
        As[a_col + 1][a_row] = av.y;
        As[a_col + 2][a_row] = av.z;
        As[a_col + 3][a_row] = av.w;
        *(float4*)&Bs[b_row][b_col] =
            *(const float4*)(B + (size_t)(k0 + b_row) * N + bcol + b_col);
        __syncthreads();
#pragma unroll
        for (int kk = 0; kk < 8; ++kk) {
            float ar[8], br[8];
#pragma unroll
            for (int i = 0; i < 8; ++i) ar[i] = As[kk][ty + i * 16];
#pragma unroll
            for (int j = 0; j < 8; ++j) br[j] = Bs[kk][tx + j * 16];
#pragma unroll
            for (int i = 0; i < 8; ++i)
#pragma unroll
                for (int j = 0; j < 8; ++j)
                    acc[i][j] = fmaf(ar[i], br[j], acc[i][j]);
        }
        __syncthreads();
    }

#pragma unroll
    for (int i = 0; i < 8; ++i) {
        int r = brow + ty + i * 16;
        if (r < M) {
            float s = dinv[r];
            size_t base = (size_t)r * N + bcol + tx;
#pragma unroll
            for (int j = 0; j < 8; ++j)
                C[base + j * 16] = acc[i][j] * s;
        }
    }
}

// ---------------- aggregation: pull-model CSR gather ----------------
// One warp per node, 128-col chunk per blockIdx.y (lane covers 4 floats).
// out[d] = relu(dinv[d] * (sum_{s in N(d)} hs[s] + hs[d]) + bias)
// layer2==0: write to outBuf. layer2==1: red.add into gsum[batch[d]].
__global__ void __launch_bounds__(256)
agg_kernel(const float* __restrict__ hs, const float* __restrict__ dinv,
           const float* __restrict__ bias, float* __restrict__ outBuf,
           const int* __restrict__ batch, float* __restrict__ gsum,
           int layer2)
{
    int warp = threadIdx.x >> 5;
    int lane = threadIdx.x & 31;
    int node = blockIdx.x * 8 + warp;          // grid.x = 12500, exact
    int coff = blockIdx.y * 128 + lane * 4;

    const float* hrow = hs + (size_t)node * H + coff;
    float4 acc = *(const float4*)hrow;          // self-loop term

    int beg = g_off[node];
    int cnt = g_ideg[node];
    const int* nb = g_csr + beg;

    int j = 0;
    for (; j + 1 < cnt; j += 2) {
        int s0 = nb[j], s1 = nb[j + 1];
        float4 v0 = *(const float4*)(hs + (size_t)s0 * H + coff);
        float4 v1 = *(const float4*)(hs + (size_t)s1 * H + coff);
        acc.x += v0.x + v1.x;
        acc.y += v0.y + v1.y;
        acc.z += v0.z + v1.z;
        acc.w += v0.w + v1.w;
    }
    if (j < cnt) {
        int s0 = nb[j];
        float4 v0 = *(const float4*)(hs + (size_t)s0 * H + coff);
        acc.x += v0.x; acc.y += v0.y; acc.z += v0.z; acc.w += v0.w;
    }

    float dv = dinv[node];
    const float4 b = *(const float4*)(bias + coff);
    float4 v;
    v.x = fmaxf(fmaf(dv, acc.x, b.x), 0.f);
    v.y = fmaxf(fmaf(dv, acc.y, b.y), 0.f);
    v.z = fmaxf(fmaf(dv, acc.z, b.z), 0.f);
    v.w = fmaxf(fmaf(dv, acc.w, b.w), 0.f);

    if (!layer2) {
        *(float4*)(outBuf + (size_t)node * H + coff) = v;
    } else {
        int g = batch[node];
        float* p = gsum + (size_t)g * H + coff;
        asm volatile("red.global.add.v4.f32 [%0], {%1, %2, %3, %4};"
                     :: "l"(p), "f"(v.x), "f"(v.y), "f"(v.z), "f"(v.w) : "memory");
    }
}

// ---------------- classifier: mean, g@Wc+bc, log_softmax(64) ----------------
__global__ void classify_kernel(const float* __restrict__ gsum, const float* __restrict__ gcnt,
                                const float* __restrict__ Wc, const float* __restrict__ bc,
                                float* __restrict__ out)
{
    int gid = blockIdx.x;
    int j = threadIdx.x;                       // 64 threads
    __shared__ float sg[H];
    __shared__ float red2[2];

    float inv = 1.0f / fmaxf(gcnt[gid], 1.0f);
    for (int c = j; c < H; c += 64) sg[c] = gsum[(size_t)gid * H + c] * inv;
    __syncthreads();

    float acc = bc[j];
#pragma unroll
    for (int c = 0; c < H; ++c)
        acc = fmaf(sg[c], Wc[c * 64 + j], acc);

    float m = acc;
#pragma unroll
    for (int o = 16; o; o >>= 1) m = fmaxf(m, __shfl_xor_sync(0xffffffffu, m, o));
    if ((j & 31) == 0) red2[j >> 5] = m;
    __syncthreads();
    m = fmaxf(red2[0], red2[1]);
    __syncthreads();

    float e = expf(acc - m);
    float s = e;
#pragma unroll
    for (int o = 16; o; o >>= 1) s += __shfl_xor_sync(0xffffffffu, s, o);
    if ((j & 31) == 0) red2[j >> 5] = s;
    __syncthreads();
    s = red2[0] + red2[1];

    out[(size_t)gid * 64 + j] = acc - m - logf(s);
}

// ---------------- launch ----------------
extern "C" void kernel_launch(void* const* d_in, const int* in_sizes, int n_in,
                              void* d_out, int out_size)
{
    const float* x     = (const float*)d_in[0];
    const int*   eidx  = (const int*)d_in[1];     // int32 (JAX canonicalized)
    const int*   batch = (const int*)d_in[2];
    const float* W1    = (const float*)d_in[3];
    const float* b1    = (const float*)d_in[4];
    const float* W2    = (const float*)d_in[5];
    const float* b2    = (const float*)d_in[6];
    const float* Wc    = (const float*)d_in[7];
    const float* bc    = (const float*)d_in[8];
    float*       out   = (float*)d_out;

    const int* src = eidx;
    const int* dst = eidx + N_EDGES;

    float *bufA, *bufC, *dinv, *gsum, *gcnt;
    cudaGetSymbolAddress((void**)&bufA, g_bufA);
    cudaGetSymbolAddress((void**)&bufC, g_bufC);
    cudaGetSymbolAddress((void**)&dinv, g_dinv);
    cudaGetSymbolAddress((void**)&gsum, g_gsum);
    cudaGetSymbolAddress((void**)&gcnt, g_gcnt);

    // prep + CSR build
    zero_kernel<<<(N_GRAPHS * H) / 256, 256>>>();
    deg_kernel<<<(N_EDGES + 255) / 256, 256>>>(dst);
    scan1_kernel<<<SCAN_NBLK, 256>>>();
    scan2_kernel<<<1, 128>>>();
    scan3_kernel<<<(N_NODES + 255) / 256, 256>>>();
    fill_kernel<<<(N_EDGES + 255) / 256, 256>>>(src, dst);
    prep_kernel<<<(N_NODES + 255) / 256, 256>>>(batch);

    dim3 ggrid((N_NODES + 127) / 128, H / 128);
    dim3 agrid(N_NODES / 8, 2);                // 12500 x 2 feature chunks

    // layer 1
    sgemm_scale<<<ggrid, 256>>>(x, W1, dinv, bufA, N_NODES, 128);
    agg_kernel<<<agrid, 256>>>(bufA, dinv, b1, bufC, batch, gsum, 0);

    // layer 2 (agg fused with relu + mean-pool accumulate)
    sgemm_scale<<<ggrid, 256>>>(bufC, W2, dinv, bufA, N_NODES, 256);
    agg_kernel<<<agrid, 256>>>(bufA, dinv, b2, nullptr, batch, gsum, 1);

    // classifier + log_softmax
    classify_kernel<<<N_GRAPHS, 64>>>(gsum, gcnt, Wc, bc, out);
}

// round 6
// speedup vs baseline: 3.0483x; 1.5135x over previous
#include <cuda_runtime.h>
#include <cuda_bf16.h>
#include <math.h>
#include <stdint.h>

#define N_NODES  100000
#define N_EDGES  1600000
#define N_GRAPHS 2048
#define H        256

#define SCAN_NBLK ((N_NODES + 1023) / 1024)   // 98 blocks of 1024

// ---------------- scratch (device globals; no allocs allowed) ----------------
__device__ int   g_ideg[N_NODES];
__device__ int   g_off[N_NODES];
__device__ int   g_cursor[N_NODES];
__device__ int   g_csr[N_EDGES];
__device__ int   g_bsum[SCAN_NBLK];
__device__ int   g_bscan[SCAN_NBLK];
__device__ float g_dinv[N_NODES];
__device__ float g_bufA[(size_t)N_NODES * H];   // hs = (h @ W) * dinv[row]  (f32)
__device__ float g_gsum[N_GRAPHS * H];
__device__ float g_gcnt[N_GRAPHS];
// bf16 split operands for tensor-core GEMMs
__device__ __nv_bfloat16 g_xh[(size_t)N_NODES * 128];
__device__ __nv_bfloat16 g_xl[(size_t)N_NODES * 128];
__device__ __nv_bfloat16 g_h1h[(size_t)N_NODES * H];
__device__ __nv_bfloat16 g_h1l[(size_t)N_NODES * H];
__device__ __nv_bfloat16 g_w1h[256 * 128];
__device__ __nv_bfloat16 g_w1l[256 * 128];
__device__ __nv_bfloat16 g_w2h[256 * 256];
__device__ __nv_bfloat16 g_w2l[256 * 256];

// ================= warp-MMA helpers (sm_80-class, compile for compute_103) ==
__device__ __forceinline__ uint32_t smem_u32(const void* p) {
    uint32_t a;
    asm("{ .reg .u64 t; cvta.to.shared.u64 t, %1; cvt.u32.u64 %0, t; }" : "=r"(a) : "l"(p));
    return a;
}
__device__ __forceinline__ void ldm_x4(uint32_t* r, uint32_t addr) {
    asm volatile("ldmatrix.sync.aligned.m8n8.x4.shared.b16 {%0,%1,%2,%3}, [%4];"
                 : "=r"(r[0]), "=r"(r[1]), "=r"(r[2]), "=r"(r[3]) : "r"(addr));
}
__device__ __forceinline__ void mma16816(float* d, const uint32_t* a, const uint32_t* b) {
    asm volatile("mma.sync.aligned.m16n8k16.row.col.f32.bf16.bf16.f32 "
                 "{%0,%1,%2,%3}, {%4,%5,%6,%7}, {%8,%9}, {%0,%1,%2,%3};"
                 : "+f"(d[0]), "+f"(d[1]), "+f"(d[2]), "+f"(d[3])
                 : "r"(a[0]), "r"(a[1]), "r"(a[2]), "r"(a[3]), "r"(b[0]), "r"(b[1]));
}
__device__ __forceinline__ void cp16(uint32_t dst, const void* src) {
    asm volatile("cp.async.ca.shared.global [%0], [%1], 16;" :: "r"(dst), "l"(src));
}
#define CP_COMMIT() asm volatile("cp.async.commit_group;" ::: "memory")
#define CP_WAIT1()  asm volatile("cp.async.wait_group 1;" ::: "memory")
#define CP_WAIT0()  asm volatile("cp.async.wait_group 0;" ::: "memory")

// ---------------- prep kernels ----------------

__global__ void zero_kernel() {
    int i = blockIdx.x * blockDim.x + threadIdx.x;     // grid covers N_GRAPHS*H = 524288
    if (i < N_NODES) { g_ideg[i] = 0; g_cursor[i] = 0; }
    if (i < N_GRAPHS * H) g_gsum[i] = 0.f;
    if (i < N_GRAPHS)     g_gcnt[i] = 0.f;
}

__global__ void deg_kernel(const int* __restrict__ dst) {
    int e = blockIdx.x * blockDim.x + threadIdx.x;
    if (e < N_EDGES) atomicAdd(&g_ideg[dst[e]], 1);
}

__global__ void scan1_kernel() {
    __shared__ int sh[256];
    int tid = threadIdx.x;
    int base = blockIdx.x * 1024 + tid * 4;
    int v[4]; int s = 0;
#pragma unroll
    for (int k = 0; k < 4; ++k) {
        int i = base + k;
        v[k] = (i < N_NODES) ? g_ideg[i] : 0;
        s += v[k];
    }
    sh[tid] = s; __syncthreads();
#pragma unroll
    for (int o = 1; o < 256; o <<= 1) {
        int t = (tid >= o) ? sh[tid - o] : 0;
        __syncthreads(); sh[tid] += t; __syncthreads();
    }
    int run = sh[tid] - s;
#pragma unroll
    for (int k = 0; k < 4; ++k) {
        int i = base + k;
        if (i < N_NODES) g_off[i] = run;
        run += v[k];
    }
    if (tid == 255) g_bsum[blockIdx.x] = sh[255];
}

__global__ void scan2_kernel() {
    __shared__ int sh[128];
    int tid = threadIdx.x;
    int v = (tid < SCAN_NBLK) ? g_bsum[tid] : 0;
    sh[tid] = v; __syncthreads();
#pragma unroll
    for (int o = 1; o < 128; o <<= 1) {
        int t = (tid >= o) ? sh[tid - o] : 0;
        __syncthreads(); sh[tid] += t; __syncthreads();
    }
    if (tid < SCAN_NBLK) g_bscan[tid] = sh[tid] - v;
}

__global__ void scan3_kernel() {
    int i = blockIdx.x * blockDim.x + threadIdx.x;
    if (i < N_NODES) g_off[i] += g_bscan[i >> 10];
}

__global__ void fill_kernel(const int* __restrict__ src, const int* __restrict__ dst) {
    int e = blockIdx.x * blockDim.x + threadIdx.x;
    if (e < N_EDGES) {
        int d = dst[e];
        int pos = g_off[d] + atomicAdd(&g_cursor[d], 1);
        g_csr[pos] = src[e];
    }
}

__global__ void prep_kernel(const int* __restrict__ batch) {
    int i = blockIdx.x * blockDim.x + threadIdx.x;
    if (i < N_NODES) {
        g_dinv[i] = rsqrtf((float)g_ideg[i] + 1.0f);
        atomicAdd(&g_gcnt[batch[i]], 1.0f);
    }
}

// split x (f32) -> hi/lo bf16; one float4 per thread
__global__ void split_x_kernel(const float* __restrict__ x) {
    int i = blockIdx.x * blockDim.x + threadIdx.x;     // N_NODES*128/4 threads exactly
    float4 v = ((const float4*)x)[i];
    __nv_bfloat16 hx = __float2bfloat16(v.x);
    __nv_bfloat16 hy = __float2bfloat16(v.y);
    __nv_bfloat16 hz = __float2bfloat16(v.z);
    __nv_bfloat16 hw = __float2bfloat16(v.w);
    __nv_bfloat16 lx = __float2bfloat16(v.x - __bfloat162float(hx));
    __nv_bfloat16 ly = __float2bfloat16(v.y - __bfloat162float(hy));
    __nv_bfloat16 lz = __float2bfloat16(v.z - __bfloat162float(hz));
    __nv_bfloat16 lw = __float2bfloat16(v.w - __bfloat162float(hw));
    ((__nv_bfloat162*)g_xh)[i * 2 + 0] = __halves2bfloat162(hx, hy);
    ((__nv_bfloat162*)g_xh)[i * 2 + 1] = __halves2bfloat162(hz, hw);
    ((__nv_bfloat162*)g_xl)[i * 2 + 0] = __halves2bfloat162(lx, ly);
    ((__nv_bfloat162*)g_xl)[i * 2 + 1] = __halves2bfloat162(lz, lw);
}

// transpose + split W[K,256] -> Wt hi/lo [256,K] bf16
__global__ void split_w_kernel(const float* __restrict__ W,
                               __nv_bfloat16* __restrict__ Th,
                               __nv_bfloat16* __restrict__ Tl, int K) {
    int i = blockIdx.x * blockDim.x + threadIdx.x;     // K*256 threads
    if (i < K * 256) {
        int k = i >> 8;
        int n = i & 255;
        float w = W[i];                 // coalesced read
        __nv_bfloat16 h = __float2bfloat16(w);
        Th[n * K + k] = h;
        Tl[n * K + k] = __float2bfloat16(w - __bfloat162float(h));
    }
}

// ======== tensor-core GEMM (mma.sync bf16, 3x precision split) ==============
// A (hi/lo): [M, K] bf16 row-major.  Wt (hi/lo): [256, K] bf16 row-major.
// C[M, 256] f32 = (A @ Wt^T) * dinv[row].
// CTA tile 128x128, BK=64, double-buffered cp.async, 8 warps (2m x 4n, 64x32).
#define GEMM_SMEM 65536   // 2 stages x (16KB A + 16KB B)

__global__ void __launch_bounds__(256, 1)
gemm_tc(const __nv_bfloat16* __restrict__ Ah, const __nv_bfloat16* __restrict__ Al,
        const __nv_bfloat16* __restrict__ Bh, const __nv_bfloat16* __restrict__ Bl,
        const float* __restrict__ dinv, float* __restrict__ C, int M, int K)
{
    extern __shared__ __align__(128) char smem[];
    const uint32_t sb = smem_u32(smem);
    const int tid = threadIdx.x;
    const int wid = tid >> 5;
    const int lane = tid & 31;
    const int tile0 = blockIdx.x * 128;      // M block
    const int nb = blockIdx.y * 128;         // N block

    const __nv_bfloat16* Alist[3] = { Ah, Ah, Al };
    const __nv_bfloat16* Blist[3] = { Bh, Bl, Bh };
    const int kcn = K >> 6;
    const int steps = 3 * kcn;

    // ---- cp.async per-thread coords: 4 rows each for A and B tiles
    const int lrow   = tid >> 3;                     // 0..31
    const int dstx   = ((tid & 7) << 4) ^ ((lrow & 7) << 4);   // swizzled 16B chunk
    const int colelm = (tid & 7) << 3;               // source col (elements)

    // ---- fragment-load lane constants (SW128: byte ^ ((row&7)<<4))
    const int warp_m = wid & 1;
    const int warp_n = wid >> 1;
    const int arow  = warp_m * 64 + (lane & 15);
    const int axor  = (lane & 7) << 4;
    const int ac8   = (lane >> 4) << 4;              // byte offset of k8 half
    const int brow  = warp_n * 32 + (lane & 7) + ((lane & 16) >> 1);
    const int bxor  = (lane & 7) << 4;
    const int bc8   = ((lane >> 3) & 1) << 4;

    float acc[4][4][4];
#pragma unroll
    for (int i = 0; i < 4; ++i)
#pragma unroll
        for (int j = 0; j < 4; ++j)
#pragma unroll
            for (int q = 0; q < 4; ++q) acc[i][j][q] = 0.f;

    // ---- tile loader
    auto load_tile = [&](int s, int st) {
        int p = (s >= kcn) + (s >= 2 * kcn);
        int kc = s - p * kcn;
        const __nv_bfloat16* Ap = Alist[p] + (kc << 6) + colelm;
        const __nv_bfloat16* Bp = Blist[p] + (kc << 6) + colelm;
        uint32_t Ad = sb + st * 32768;
        uint32_t Bd = Ad + 16384;
#pragma unroll
        for (int j = 0; j < 4; ++j) {
            int row = lrow + (j << 5);
            int gr = tile0 + row; if (gr >= M) gr = M - 1;
            cp16(Ad + row * 128 + dstx, Ap + (size_t)gr * K);
            cp16(Bd + row * 128 + dstx, Bp + (size_t)(nb + row) * K);
        }
    };

    load_tile(0, 0);
    CP_COMMIT();

    for (int s = 0; s < steps; ++s) {
        int st = s & 1;
        if (s + 1 < steps) {
            load_tile(s + 1, st ^ 1);
            CP_COMMIT();
            CP_WAIT1();
        } else {
            CP_WAIT0();
        }
        __syncthreads();

        uint32_t Abase = sb + st * 32768;
        uint32_t Bbase = Abase + 16384;
#pragma unroll
        for (int k16 = 0; k16 < 4; ++k16) {
            uint32_t a[4][4], b[2][4];
            int cA = ((k16 << 5) + ac8) ^ axor;
            uint32_t aaddr = Abase + arow * 128 + cA;
#pragma unroll
            for (int tm = 0; tm < 4; ++tm) ldm_x4(a[tm], aaddr + tm * 2048);
            int cB = ((k16 << 5) + bc8) ^ bxor;
            uint32_t baddr = Bbase + brow * 128 + cB;
#pragma unroll
            for (int t2 = 0; t2 < 2; ++t2) ldm_x4(b[t2], baddr + t2 * 2048);
#pragma unroll
            for (int tm = 0; tm < 4; ++tm)
#pragma unroll
                for (int tn = 0; tn < 4; ++tn)
                    mma16816(acc[tm][tn], a[tm], &b[tn >> 1][(tn & 1) * 2]);
        }
        __syncthreads();
    }

    // ---- epilogue: scale by dinv[row], store f32
    const int mrow0 = tile0 + warp_m * 64 + (lane >> 2);
    const int ncol0 = nb + warp_n * 32 + (lane & 3) * 2;
#pragma unroll
    for (int tm = 0; tm < 4; ++tm) {
        int r0 = mrow0 + tm * 16;
        int r1 = r0 + 8;
        float dv0 = (r0 < M) ? dinv[r0] : 0.f;
        float dv1 = (r1 < M) ? dinv[r1] : 0.f;
#pragma unroll
        for (int tn = 0; tn < 4; ++tn) {
            int c = ncol0 + tn * 8;
            if (r0 < M) {
                float2 o0 = make_float2(acc[tm][tn][0] * dv0, acc[tm][tn][1] * dv0);
                *(float2*)(C + (size_t)r0 * H + c) = o0;
            }
            if (r1 < M) {
                float2 o1 = make_float2(acc[tm][tn][2] * dv1, acc[tm][tn][3] * dv1);
                *(float2*)(C + (size_t)r1 * H + c) = o1;
            }
        }
    }
}

// ---------------- aggregation: pull-model CSR gather ----------------
// layer2==0: out = relu(...) -> split bf16 hi/lo (feeds layer-2 tensor GEMM)
// layer2==1: red.add relu(...) into gsum[batch[d]]
__global__ void __launch_bounds__(256)
agg_kernel(const float* __restrict__ hs, const float* __restrict__ dinv,
           const float* __restrict__ bias,
           __nv_bfloat16* __restrict__ outH, __nv_bfloat16* __restrict__ outL,
           const int* __restrict__ batch, float* __restrict__ gsum,
           int layer2)
{
    int warp = threadIdx.x >> 5;
    int lane = threadIdx.x & 31;
    int node = blockIdx.x * 8 + warp;          // grid.x = 12500, exact
    int coff = blockIdx.y * 128 + lane * 4;

    const float* hrow = hs + (size_t)node * H + coff;
    float4 acc = *(const float4*)hrow;          // self-loop term

    int beg = g_off[node];
    int cnt = g_ideg[node];
    const int* nb = g_csr + beg;

    int j = 0;
    for (; j + 1 < cnt; j += 2) {
        int s0 = nb[j], s1 = nb[j + 1];
        float4 v0 = *(const float4*)(hs + (size_t)s0 * H + coff);
        float4 v1 = *(const float4*)(hs + (size_t)s1 * H + coff);
        acc.x += v0.x + v1.x;
        acc.y += v0.y + v1.y;
        acc.z += v0.z + v1.z;
        acc.w += v0.w + v1.w;
    }
    if (j < cnt) {
        int s0 = nb[j];
        float4 v0 = *(const float4*)(hs + (size_t)s0 * H + coff);
        acc.x += v0.x; acc.y += v0.y; acc.z += v0.z; acc.w += v0.w;
    }

    float dv = dinv[node];
    const float4 b = *(const float4*)(bias + coff);
    float4 v;
    v.x = fmaxf(fmaf(dv, acc.x, b.x), 0.f);
    v.y = fmaxf(fmaf(dv, acc.y, b.y), 0.f);
    v.z = fmaxf(fmaf(dv, acc.z, b.z), 0.f);
    v.w = fmaxf(fmaf(dv, acc.w, b.w), 0.f);

    if (!layer2) {
        __nv_bfloat16 hx = __float2bfloat16(v.x);
        __nv_bfloat16 hy = __float2bfloat16(v.y);
        __nv_bfloat16 hz = __float2bfloat16(v.z);
        __nv_bfloat16 hw = __float2bfloat16(v.w);
        __nv_bfloat16 lx = __float2bfloat16(v.x - __bfloat162float(hx));
        __nv_bfloat16 ly = __float2bfloat16(v.y - __bfloat162float(hy));
        __nv_bfloat16 lz = __float2bfloat16(v.z - __bfloat162float(hz));
        __nv_bfloat16 lw = __float2bfloat16(v.w - __bfloat162float(hw));
        size_t base = (size_t)node * H + coff;
        ((__nv_bfloat162*)(outH + base))[0] = __halves2bfloat162(hx, hy);
        ((__nv_bfloat162*)(outH + base))[1] = __halves2bfloat162(hz, hw);
        ((__nv_bfloat162*)(outL + base))[0] = __halves2bfloat162(lx, ly);
        ((__nv_bfloat162*)(outL + base))[1] = __halves2bfloat162(lz, lw);
    } else {
        int g = batch[node];
        float* p = gsum + (size_t)g * H + coff;
        asm volatile("red.global.add.v4.f32 [%0], {%1, %2, %3, %4};"
                     :: "l"(p), "f"(v.x), "f"(v.y), "f"(v.z), "f"(v.w) : "memory");
    }
}

// ---------------- classifier: mean, g@Wc+bc, log_softmax(64) ----------------
__global__ void classify_kernel(const float* __restrict__ gsum, const float* __restrict__ gcnt,
                                const float* __restrict__ Wc, const float* __restrict__ bc,
                                float* __restrict__ out)
{
    int gid = blockIdx.x;
    int j = threadIdx.x;                       // 64 threads
    __shared__ float sg[H];
    __shared__ float red2[2];

    float inv = 1.0f / fmaxf(gcnt[gid], 1.0f);
    for (int c = j; c < H; c += 64) sg[c] = gsum[(size_t)gid * H + c] * inv;
    __syncthreads();

    float acc = bc[j];
#pragma unroll
    for (int c = 0; c < H; ++c)
        acc = fmaf(sg[c], Wc[c * 64 + j], acc);

    float m = acc;
#pragma unroll
    for (int o = 16; o; o >>= 1) m = fmaxf(m, __shfl_xor_sync(0xffffffffu, m, o));
    if ((j & 31) == 0) red2[j >> 5] = m;
    __syncthreads();
    m = fmaxf(red2[0], red2[1]);
    __syncthreads();

    float e = expf(acc - m);
    float s = e;
#pragma unroll
    for (int o = 16; o; o >>= 1) s += __shfl_xor_sync(0xffffffffu, s, o);
    if ((j & 31) == 0) red2[j >> 5] = s;
    __syncthreads();
    s = red2[0] + red2[1];

    out[(size_t)gid * 64 + j] = acc - m - logf(s);
}

// ---------------- launch ----------------
extern "C" void kernel_launch(void* const* d_in, const int* in_sizes, int n_in,
                              void* d_out, int out_size)
{
    const float* x     = (const float*)d_in[0];
    const int*   eidx  = (const int*)d_in[1];     // int32 (JAX canonicalized)
    const int*   batch = (const int*)d_in[2];
    const float* W1    = (const float*)d_in[3];
    const float* b1    = (const float*)d_in[4];
    const float* W2    = (const float*)d_in[5];
    const float* b2    = (const float*)d_in[6];
    const float* Wc    = (const float*)d_in[7];
    const float* bc    = (const float*)d_in[8];
    float*       out   = (float*)d_out;

    const int* src = eidx;
    const int* dst = eidx + N_EDGES;

    float *bufA, *dinv, *gsum, *gcnt;
    __nv_bfloat16 *xh, *xl, *h1h, *h1l, *w1h, *w1l, *w2h, *w2l;
    cudaGetSymbolAddress((void**)&bufA, g_bufA);
    cudaGetSymbolAddress((void**)&dinv, g_dinv);
    cudaGetSymbolAddress((void**)&gsum, g_gsum);
    cudaGetSymbolAddress((void**)&gcnt, g_gcnt);
    cudaGetSymbolAddress((void**)&xh,  g_xh);
    cudaGetSymbolAddress((void**)&xl,  g_xl);
    cudaGetSymbolAddress((void**)&h1h, g_h1h);
    cudaGetSymbolAddress((void**)&h1l, g_h1l);
    cudaGetSymbolAddress((void**)&w1h, g_w1h);
    cudaGetSymbolAddress((void**)&w1l, g_w1l);
    cudaGetSymbolAddress((void**)&w2h, g_w2h);
    cudaGetSymbolAddress((void**)&w2l, g_w2l);

    cudaFuncSetAttribute(gemm_tc, cudaFuncAttributeMaxDynamicSharedMemorySize, GEMM_SMEM);

    // prep + CSR build
    zero_kernel<<<(N_GRAPHS * H) / 256, 256>>>();
    deg_kernel<<<(N_EDGES + 255) / 256, 256>>>(dst);
    scan1_kernel<<<SCAN_NBLK, 256>>>();
    scan2_kernel<<<1, 128>>>();
    scan3_kernel<<<(N_NODES + 255) / 256, 256>>>();
    fill_kernel<<<(N_EDGES + 255) / 256, 256>>>(src, dst);
    prep_kernel<<<(N_NODES + 255) / 256, 256>>>(batch);

    // operand splits
    split_x_kernel<<<(N_NODES * 128 / 4) / 256, 256>>>(x);
    split_w_kernel<<<(128 * 256 + 255) / 256, 256>>>(W1, w1h, w1l, 128);
    split_w_kernel<<<(256 * 256 + 255) / 256, 256>>>(W2, w2h, w2l, 256);

    const int ntiles = (N_NODES + 127) / 128;   // 782
    dim3 ggrid(ntiles, 2);                      // N blocks of 128
    dim3 agrid(N_NODES / 8, 2);                 // 12500 x 2 feature chunks

    // layer 1
    gemm_tc<<<ggrid, 256, GEMM_SMEM>>>(xh, xl, w1h, w1l, dinv, bufA, N_NODES, 128);
    agg_kernel<<<agrid, 256>>>(bufA, dinv, b1, h1h, h1l, batch, gsum, 0);

    // layer 2 (agg fused with relu + mean-pool accumulate)
    gemm_tc<<<ggrid, 256, GEMM_SMEM>>>(h1h, h1l, w2h, w2l, dinv, bufA, N_NODES, 256);
    agg_kernel<<<agrid, 256>>>(bufA, dinv, b2, nullptr, nullptr, batch, gsum, 1);

    // classifier + log_softmax
    classify_kernel<<<N_GRAPHS, 64>>>(gsum, gcnt, Wc, bc, out);
}

// round 7
// speedup vs baseline: 3.2904x; 1.0794x over previous
#include <cuda_runtime.h>
#include <cuda_bf16.h>
#include <math.h>
#include <stdint.h>

#define N_NODES  100000
#define N_EDGES  1600000
#define N_GRAPHS 2048
#define H        256

#define SCAN_NBLK ((N_NODES + 1023) / 1024)   // 98 blocks of 1024

// ---------------- scratch (device globals; no allocs allowed) ----------------
__device__ int   g_ideg[N_NODES];
__device__ int   g_off[N_NODES];
__device__ int   g_cursor[N_NODES];
__device__ int   g_csr[N_EDGES];
__device__ int   g_bsum[SCAN_NBLK];
__device__ int   g_bscan[SCAN_NBLK];
__device__ float g_dinv[N_NODES];
__device__ float g_bufA[(size_t)N_NODES * H];   // hs = (h @ W) * dinv[row]  (f32)
__device__ float g_gsum[N_GRAPHS * H];
__device__ float g_gcnt[N_GRAPHS];
// bf16 split operands for tensor-core GEMMs
__device__ __nv_bfloat16 g_xh[(size_t)N_NODES * 128];
__device__ __nv_bfloat16 g_xl[(size_t)N_NODES * 128];
__device__ __nv_bfloat16 g_h1h[(size_t)N_NODES * H];
__device__ __nv_bfloat16 g_h1l[(size_t)N_NODES * H];
__device__ __nv_bfloat16 g_w1h[256 * 128];
__device__ __nv_bfloat16 g_w1l[256 * 128];
__device__ __nv_bfloat16 g_w2h[256 * 256];
__device__ __nv_bfloat16 g_w2l[256 * 256];

// ================= warp-MMA helpers (sm_80-class, compile for compute_103) ==
__device__ __forceinline__ uint32_t smem_u32(const void* p) {
    uint32_t a;
    asm("{ .reg .u64 t; cvta.to.shared.u64 t, %1; cvt.u32.u64 %0, t; }" : "=r"(a) : "l"(p));
    return a;
}
__device__ __forceinline__ void ldm_x4(uint32_t* r, uint32_t addr) {
    asm volatile("ldmatrix.sync.aligned.m8n8.x4.shared.b16 {%0,%1,%2,%3}, [%4];"
                 : "=r"(r[0]), "=r"(r[1]), "=r"(r[2]), "=r"(r[3]) : "r"(addr));
}
__device__ __forceinline__ void mma16816(float* d, const uint32_t* a, const uint32_t* b) {
    asm volatile("mma.sync.aligned.m16n8k16.row.col.f32.bf16.bf16.f32 "
                 "{%0,%1,%2,%3}, {%4,%5,%6,%7}, {%8,%9}, {%0,%1,%2,%3};"
                 : "+f"(d[0]), "+f"(d[1]), "+f"(d[2]), "+f"(d[3])
                 : "r"(a[0]), "r"(a[1]), "r"(a[2]), "r"(a[3]), "r"(b[0]), "r"(b[1]));
}
__device__ __forceinline__ void cp16(uint32_t dst, const void* src) {
    asm volatile("cp.async.ca.shared.global [%0], [%1], 16;" :: "r"(dst), "l"(src));
}
#define CP_COMMIT() asm volatile("cp.async.commit_group;" ::: "memory")
#define CP_WAIT1()  asm volatile("cp.async.wait_group 1;" ::: "memory")
#define CP_WAIT0()  asm volatile("cp.async.wait_group 0;" ::: "memory")

// ---------------- prep kernels ----------------

__global__ void zero_kernel() {
    int i = blockIdx.x * blockDim.x + threadIdx.x;     // grid covers N_GRAPHS*H = 524288
    if (i < N_NODES) { g_ideg[i] = 0; g_cursor[i] = 0; }
    if (i < N_GRAPHS * H) g_gsum[i] = 0.f;
    if (i < N_GRAPHS)     g_gcnt[i] = 0.f;
}

__global__ void deg_kernel(const int* __restrict__ dst) {
    int e = blockIdx.x * blockDim.x + threadIdx.x;
    if (e < N_EDGES) atomicAdd(&g_ideg[dst[e]], 1);
}

__global__ void scan1_kernel() {
    __shared__ int sh[256];
    int tid = threadIdx.x;
    int base = blockIdx.x * 1024 + tid * 4;
    int v[4]; int s = 0;
#pragma unroll
    for (int k = 0; k < 4; ++k) {
        int i = base + k;
        v[k] = (i < N_NODES) ? g_ideg[i] : 0;
        s += v[k];
    }
    sh[tid] = s; __syncthreads();
#pragma unroll
    for (int o = 1; o < 256; o <<= 1) {
        int t = (tid >= o) ? sh[tid - o] : 0;
        __syncthreads(); sh[tid] += t; __syncthreads();
    }
    int run = sh[tid] - s;
#pragma unroll
    for (int k = 0; k < 4; ++k) {
        int i = base + k;
        if (i < N_NODES) g_off[i] = run;
        run += v[k];
    }
    if (tid == 255) g_bsum[blockIdx.x] = sh[255];
}

__global__ void scan2_kernel() {
    __shared__ int sh[128];
    int tid = threadIdx.x;
    int v = (tid < SCAN_NBLK) ? g_bsum[tid] : 0;
    sh[tid] = v; __syncthreads();
#pragma unroll
    for (int o = 1; o < 128; o <<= 1) {
        int t = (tid >= o) ? sh[tid - o] : 0;
        __syncthreads(); sh[tid] += t; __syncthreads();
    }
    if (tid < SCAN_NBLK) g_bscan[tid] = sh[tid] - v;
}

__global__ void scan3_kernel() {
    int i = blockIdx.x * blockDim.x + threadIdx.x;
    if (i < N_NODES) g_off[i] += g_bscan[i >> 10];
}

__global__ void fill_kernel(const int* __restrict__ src, const int* __restrict__ dst) {
    int e = blockIdx.x * blockDim.x + threadIdx.x;
    if (e < N_EDGES) {
        int d = dst[e];
        int pos = g_off[d] + atomicAdd(&g_cursor[d], 1);
        g_csr[pos] = src[e];
    }
}

__global__ void prep_kernel(const int* __restrict__ batch) {
    int i = blockIdx.x * blockDim.x + threadIdx.x;
    if (i < N_NODES) {
        g_dinv[i] = rsqrtf((float)g_ideg[i] + 1.0f);
        atomicAdd(&g_gcnt[batch[i]], 1.0f);
    }
}

// split x (f32) -> hi/lo bf16; one float4 per thread
__global__ void split_x_kernel(const float* __restrict__ x) {
    int i = blockIdx.x * blockDim.x + threadIdx.x;     // N_NODES*128/4 threads exactly
    float4 v = ((const float4*)x)[i];
    __nv_bfloat16 hx = __float2bfloat16(v.x);
    __nv_bfloat16 hy = __float2bfloat16(v.y);
    __nv_bfloat16 hz = __float2bfloat16(v.z);
    __nv_bfloat16 hw = __float2bfloat16(v.w);
    __nv_bfloat16 lx = __float2bfloat16(v.x - __bfloat162float(hx));
    __nv_bfloat16 ly = __float2bfloat16(v.y - __bfloat162float(hy));
    __nv_bfloat16 lz = __float2bfloat16(v.z - __bfloat162float(hz));
    __nv_bfloat16 lw = __float2bfloat16(v.w - __bfloat162float(hw));
    ((__nv_bfloat162*)g_xh)[i * 2 + 0] = __halves2bfloat162(hx, hy);
    ((__nv_bfloat162*)g_xh)[i * 2 + 1] = __halves2bfloat162(hz, hw);
    ((__nv_bfloat162*)g_xl)[i * 2 + 0] = __halves2bfloat162(lx, ly);
    ((__nv_bfloat162*)g_xl)[i * 2 + 1] = __halves2bfloat162(lz, lw);
}

// transpose + split W[K,256] -> Wt hi/lo [256,K] bf16
__global__ void split_w_kernel(const float* __restrict__ W,
                               __nv_bfloat16* __restrict__ Th,
                               __nv_bfloat16* __restrict__ Tl, int K) {
    int i = blockIdx.x * blockDim.x + threadIdx.x;     // K*256 threads
    if (i < K * 256) {
        int k = i >> 8;
        int n = i & 255;
        float w = W[i];                 // coalesced read
        __nv_bfloat16 h = __float2bfloat16(w);
        Th[n * K + k] = h;
        Tl[n * K + k] = __float2bfloat16(w - __bfloat162float(h));
    }
}

// ======== tensor-core GEMM (mma.sync bf16, fused 3x precision split) ========
// A (hi/lo): [M, K] bf16 row-major.  Wt (hi/lo): [256, K] bf16 row-major.
// C[M, 256] f32 = (A @ Wt^T) * dinv[row].
// CTA tile 128x128, BK=64. Per K-chunk: load Ah/Al/Bh/Bl tiles together, then
// run 3 MMA sweeps (Ah*Bh, Ah*Bl, Al*Bh) from SMEM — A loaded ONCE per chunk.
#define ST_AH 0
#define ST_AL 16384
#define ST_BH 32768
#define ST_BL 49152
#define STAGE 65536
#define GEMM_SMEM (2 * STAGE)   // 131072

__global__ void __launch_bounds__(256, 1)
gemm_tc(const __nv_bfloat16* __restrict__ Ah, const __nv_bfloat16* __restrict__ Al,
        const __nv_bfloat16* __restrict__ Bh, const __nv_bfloat16* __restrict__ Bl,
        const float* __restrict__ dinv, float* __restrict__ C, int M, int K)
{
    extern __shared__ __align__(128) char smem[];
    const uint32_t sb = smem_u32(smem);
    const int tid = threadIdx.x;
    const int wid = tid >> 5;
    const int lane = tid & 31;
    const int tile0 = blockIdx.x * 128;      // M block
    const int nb = blockIdx.y * 128;         // N block

    const int kcn = K >> 6;

    // ---- cp.async per-thread coords: 4 rows each per tile
    const int lrow   = tid >> 3;                     // 0..31
    const int dstx   = ((tid & 7) << 4) ^ ((lrow & 7) << 4);   // swizzled 16B chunk
    const int colelm = (tid & 7) << 3;               // source col (elements)

    // ---- fragment-load lane constants (SW128: byte ^ ((row&7)<<4))
    const int warp_m = wid & 1;
    const int warp_n = wid >> 1;
    const int arow  = warp_m * 64 + (lane & 15);
    const int axor  = (lane & 7) << 4;
    const int ac8   = (lane >> 4) << 4;              // byte offset of k8 half
    const int brow  = warp_n * 32 + (lane & 7) + ((lane & 16) >> 1);
    const int bxor  = (lane & 7) << 4;
    const int bc8   = ((lane >> 3) & 1) << 4;

    float acc[4][4][4];
#pragma unroll
    for (int i = 0; i < 4; ++i)
#pragma unroll
        for (int j = 0; j < 4; ++j)
#pragma unroll
            for (int q = 0; q < 4; ++q) acc[i][j][q] = 0.f;

    // ---- stage loader: all 4 operand tiles at K-chunk kc
    auto load_stage = [&](int kc, int st) {
        const int kofs = (kc << 6) + colelm;
        uint32_t base = sb + st * STAGE;
#pragma unroll
        for (int j = 0; j < 4; ++j) {
            int row = lrow + (j << 5);
            int gr = tile0 + row; if (gr >= M) gr = M - 1;
            uint32_t rb = base + row * 128 + dstx;
            cp16(rb + ST_AH, Ah + (size_t)gr * K + kofs);
            cp16(rb + ST_AL, Al + (size_t)gr * K + kofs);
            cp16(rb + ST_BH, Bh + (size_t)(nb + row) * K + kofs);
            cp16(rb + ST_BL, Bl + (size_t)(nb + row) * K + kofs);
        }
    };

    load_stage(0, 0);
    CP_COMMIT();

    for (int ch = 0; ch < kcn; ++ch) {
        int st = ch & 1;
        if (ch + 1 < kcn) {
            load_stage(ch + 1, st ^ 1);
            CP_COMMIT();
            CP_WAIT1();
        } else {
            CP_WAIT0();
        }
        __syncthreads();

        uint32_t base = sb + st * STAGE;
        // 3 split passes from resident tiles: (Ah,Bh), (Ah,Bl), (Al,Bh)
#pragma unroll
        for (int p = 0; p < 3; ++p) {
            uint32_t Abase = base + ((p == 2) ? ST_AL : ST_AH);
            uint32_t Bbase = base + ((p == 1) ? ST_BL : ST_BH);
#pragma unroll
            for (int k16 = 0; k16 < 4; ++k16) {
                uint32_t a[4][4], b[2][4];
                int cA = ((k16 << 5) + ac8) ^ axor;
                uint32_t aaddr = Abase + arow * 128 + cA;
#pragma unroll
                for (int tm = 0; tm < 4; ++tm) ldm_x4(a[tm], aaddr + tm * 2048);
                int cB = ((k16 << 5) + bc8) ^ bxor;
                uint32_t baddr = Bbase + brow * 128 + cB;
#pragma unroll
                for (int t2 = 0; t2 < 2; ++t2) ldm_x4(b[t2], baddr + t2 * 2048);
#pragma unroll
                for (int tm = 0; tm < 4; ++tm)
#pragma unroll
                    for (int tn = 0; tn < 4; ++tn)
                        mma16816(acc[tm][tn], a[tm], &b[tn >> 1][(tn & 1) * 2]);
            }
        }
        __syncthreads();
    }

    // ---- epilogue: scale by dinv[row], store f32
    const int mrow0 = tile0 + warp_m * 64 + (lane >> 2);
    const int ncol0 = nb + warp_n * 32 + (lane & 3) * 2;
#pragma unroll
    for (int tm = 0; tm < 4; ++tm) {
        int r0 = mrow0 + tm * 16;
        int r1 = r0 + 8;
        float dv0 = (r0 < M) ? dinv[r0] : 0.f;
        float dv1 = (r1 < M) ? dinv[r1] : 0.f;
#pragma unroll
        for (int tn = 0; tn < 4; ++tn) {
            int c = ncol0 + tn * 8;
            if (r0 < M) {
                float2 o0 = make_float2(acc[tm][tn][0] * dv0, acc[tm][tn][1] * dv0);
                *(float2*)(C + (size_t)r0 * H + c) = o0;
            }
            if (r1 < M) {
                float2 o1 = make_float2(acc[tm][tn][2] * dv1, acc[tm][tn][3] * dv1);
                *(float2*)(C + (size_t)r1 * H + c) = o1;
            }
        }
    }
}

// ---------------- aggregation: pull-model CSR gather ----------------
// layer2==0: out = relu(...) -> split bf16 hi/lo (feeds layer-2 tensor GEMM)
// layer2==1: red.add relu(...) into gsum[batch[d]]
__global__ void __launch_bounds__(256)
agg_kernel(const float* __restrict__ hs, const float* __restrict__ dinv,
           const float* __restrict__ bias,
           __nv_bfloat16* __restrict__ outH, __nv_bfloat16* __restrict__ outL,
           const int* __restrict__ batch, float* __restrict__ gsum,
           int layer2)
{
    int warp = threadIdx.x >> 5;
    int lane = threadIdx.x & 31;
    int node = blockIdx.x * 8 + warp;          // grid.x = 12500, exact
    int coff = blockIdx.y * 128 + lane * 4;

    const float* hrow = hs + (size_t)node * H + coff;
    float4 acc = *(const float4*)hrow;          // self-loop term

    int beg = g_off[node];
    int cnt = g_ideg[node];
    const int* nb = g_csr + beg;

    int j = 0;
    for (; j + 1 < cnt; j += 2) {
        int s0 = nb[j], s1 = nb[j + 1];
        float4 v0 = *(const float4*)(hs + (size_t)s0 * H + coff);
        float4 v1 = *(const float4*)(hs + (size_t)s1 * H + coff);
        acc.x += v0.x + v1.x;
        acc.y += v0.y + v1.y;
        acc.z += v0.z + v1.z;
        acc.w += v0.w + v1.w;
    }
    if (j < cnt) {
        int s0 = nb[j];
        float4 v0 = *(const float4*)(hs + (size_t)s0 * H + coff);
        acc.x += v0.x; acc.y += v0.y; acc.z += v0.z; acc.w += v0.w;
    }

    float dv = dinv[node];
    const float4 b = *(const float4*)(bias + coff);
    float4 v;
    v.x = fmaxf(fmaf(dv, acc.x, b.x), 0.f);
    v.y = fmaxf(fmaf(dv, acc.y, b.y), 0.f);
    v.z = fmaxf(fmaf(dv, acc.z, b.z), 0.f);
    v.w = fmaxf(fmaf(dv, acc.w, b.w), 0.f);

    if (!layer2) {
        __nv_bfloat16 hx = __float2bfloat16(v.x);
        __nv_bfloat16 hy = __float2bfloat16(v.y);
        __nv_bfloat16 hz = __float2bfloat16(v.z);
        __nv_bfloat16 hw = __float2bfloat16(v.w);
        __nv_bfloat16 lx = __float2bfloat16(v.x - __bfloat162float(hx));
        __nv_bfloat16 ly = __float2bfloat16(v.y - __bfloat162float(hy));
        __nv_bfloat16 lz = __float2bfloat16(v.z - __bfloat162float(hz));
        __nv_bfloat16 lw = __float2bfloat16(v.w - __bfloat162float(hw));
        size_t base = (size_t)node * H + coff;
        ((__nv_bfloat162*)(outH + base))[0] = __halves2bfloat162(hx, hy);
        ((__nv_bfloat162*)(outH + base))[1] = __halves2bfloat162(hz, hw);
        ((__nv_bfloat162*)(outL + base))[0] = __halves2bfloat162(lx, ly);
        ((__nv_bfloat162*)(outL + base))[1] = __halves2bfloat162(lz, lw);
    } else {
        int g = batch[node];
        float* p = gsum + (size_t)g * H + coff;
        asm volatile("red.global.add.v4.f32 [%0], {%1, %2, %3, %4};"
                     :: "l"(p), "f"(v.x), "f"(v.y), "f"(v.z), "f"(v.w) : "memory");
    }
}

// ---------------- classifier: mean, g@Wc+bc, log_softmax(64) ----------------
__global__ void classify_kernel(const float* __restrict__ gsum, const float* __restrict__ gcnt,
                                const float* __restrict__ Wc, const float* __restrict__ bc,
                                float* __restrict__ out)
{
    int gid = blockIdx.x;
    int j = threadIdx.x;                       // 64 threads
    __shared__ float sg[H];
    __shared__ float red2[2];

    float inv = 1.0f / fmaxf(gcnt[gid], 1.0f);
    for (int c = j; c < H; c += 64) sg[c] = gsum[(size_t)gid * H + c] * inv;
    __syncthreads();

    float acc = bc[j];
#pragma unroll
    for (int c = 0; c < H; ++c)
        acc = fmaf(sg[c], Wc[c * 64 + j], acc);

    float m = acc;
#pragma unroll
    for (int o = 16; o; o >>= 1) m = fmaxf(m, __shfl_xor_sync(0xffffffffu, m, o));
    if ((j & 31) == 0) red2[j >> 5] = m;
    __syncthreads();
    m = fmaxf(red2[0], red2[1]);
    __syncthreads();

    float e = expf(acc - m);
    float s = e;
#pragma unroll
    for (int o = 16; o; o >>= 1) s += __shfl_xor_sync(0xffffffffu, s, o);
    if ((j & 31) == 0) red2[j >> 5] = s;
    __syncthreads();
    s = red2[0] + red2[1];

    out[(size_t)gid * 64 + j] = acc - m - logf(s);
}

// ---------------- launch ----------------
extern "C" void kernel_launch(void* const* d_in, const int* in_sizes, int n_in,
                              void* d_out, int out_size)
{
    const float* x     = (const float*)d_in[0];
    const int*   eidx  = (const int*)d_in[1];     // int32 (JAX canonicalized)
    const int*   batch = (const int*)d_in[2];
    const float* W1    = (const float*)d_in[3];
    const float* b1    = (const float*)d_in[4];
    const float* W2    = (const float*)d_in[5];
    const float* b2    = (const float*)d_in[6];
    const float* Wc    = (const float*)d_in[7];
    const float* bc    = (const float*)d_in[8];
    float*       out   = (float*)d_out;

    const int* src = eidx;
    const int* dst = eidx + N_EDGES;

    float *bufA, *dinv, *gsum, *gcnt;
    __nv_bfloat16 *xh, *xl, *h1h, *h1l, *w1h, *w1l, *w2h, *w2l;
    cudaGetSymbolAddress((void**)&bufA, g_bufA);
    cudaGetSymbolAddress((void**)&dinv, g_dinv);
    cudaGetSymbolAddress((void**)&gsum, g_gsum);
    cudaGetSymbolAddress((void**)&gcnt, g_gcnt);
    cudaGetSymbolAddress((void**)&xh,  g_xh);
    cudaGetSymbolAddress((void**)&xl,  g_xl);
    cudaGetSymbolAddress((void**)&h1h, g_h1h);
    cudaGetSymbolAddress((void**)&h1l, g_h1l);
    cudaGetSymbolAddress((void**)&w1h, g_w1h);
    cudaGetSymbolAddress((void**)&w1l, g_w1l);
    cudaGetSymbolAddress((void**)&w2h, g_w2h);
    cudaGetSymbolAddress((void**)&w2l, g_w2l);

    cudaFuncSetAttribute(gemm_tc, cudaFuncAttributeMaxDynamicSharedMemorySize, GEMM_SMEM);

    // prep + CSR build
    zero_kernel<<<(N_GRAPHS * H) / 256, 256>>>();
    deg_kernel<<<(N_EDGES + 255) / 256, 256>>>(dst);
    scan1_kernel<<<SCAN_NBLK, 256>>>();
    scan2_kernel<<<1, 128>>>();
    scan3_kernel<<<(N_NODES + 255) / 256, 256>>>();
    fill_kernel<<<(N_EDGES + 255) / 256, 256>>>(src, dst);
    prep_kernel<<<(N_NODES + 255) / 256, 256>>>(batch);

    // operand splits
    split_x_kernel<<<(N_NODES * 128 / 4) / 256, 256>>>(x);
    split_w_kernel<<<(128 * 256 + 255) / 256, 256>>>(W1, w1h, w1l, 128);
    split_w_kernel<<<(256 * 256 + 255) / 256, 256>>>(W2, w2h, w2l, 256);

    const int ntiles = (N_NODES + 127) / 128;   // 782
    dim3 ggrid(ntiles, 2);                      // N blocks of 128
    dim3 agrid(N_NODES / 8, 2);                 // 12500 x 2 feature chunks

    // layer 1
    gemm_tc<<<ggrid, 256, GEMM_SMEM>>>(xh, xl, w1h, w1l, dinv, bufA, N_NODES, 128);
    agg_kernel<<<agrid, 256>>>(bufA, dinv, b1, h1h, h1l, batch, gsum, 0);

    // layer 2 (agg fused with relu + mean-pool accumulate)
    gemm_tc<<<ggrid, 256, GEMM_SMEM>>>(h1h, h1l, w2h, w2l, dinv, bufA, N_NODES, 256);
    agg_kernel<<<agrid, 256>>>(bufA, dinv, b2, nullptr, nullptr, batch, gsum, 1);

    // classifier + log_softmax
    classify_kernel<<<N_GRAPHS, 64>>>(gsum, gcnt, Wc, bc, out);
}